// round 15
// baseline (speedup 1.0000x reference)
#include <cuda_runtime.h>
#include <cuda_fp16.h>

#define N_NODES  100000
#define N_EDGES  1600000
#define N_GRAPHS 64
#define ELL_W    64          // max in-degree pad (P(deg>64) ~ 1e-20)
#define SENT     N_NODES     // sentinel node id -> zero row

// ---------------- scratch (device globals; zero-init at load) ----------------
// INVARIANT: g_degout, g_degin, g_gsum, g_done are zero on entry to every
// kernel_launch call and are restored to zero by the end of it.
// Row SENT (=N_NODES) of g_x1h/g_h1s/g_z3h is NEVER written -> stays zero.
__device__ __align__(256) __half2  g_x1h  [(N_NODES + 1) * 4];
__device__ __align__(256) __half2  g_h1s  [(N_NODES + 1) * 8];
__device__ __align__(256) __half2  g_z3h  [(N_NODES + 1) * 8];
__device__ __align__(256) float    g_invin [N_NODES];
__device__ __align__(256) float    g_invout[N_NODES];
__device__ __align__(256) int      g_degout[N_NODES];
__device__ __align__(256) int      g_degin [N_NODES];
__device__ __align__(256) int      g_ell   [(size_t)N_NODES * ELL_W];
__device__ __align__(256) float    g_gsum [N_GRAPHS * 10];
__device__                int      g_done;

__device__ __forceinline__ __half2 h2(unsigned b) {
    return *reinterpret_cast<__half2*>(&b);
}
__device__ __forceinline__ void acc_f(float& a0, float& a1, __half2 h) {
    float2 f = __half22float2(h);
    a0 += f.x; a1 += f.y;
}
__device__ __forceinline__ void tree4(float& a0, float& a1,
                                      unsigned b0, unsigned b1,
                                      unsigned b2, unsigned b3) {
    __half2 t0 = __hadd2(h2(b0), h2(b1));
    __half2 t1 = __hadd2(h2(b2), h2(b3));
    acc_f(a0, a1, __hadd2(t0, t1));
}
__device__ __forceinline__ void tree2(float& a0, float& a1,
                                      unsigned b0, unsigned b1) {
    acc_f(a0, a1, __hadd2(h2(b0), h2(b1)));
}

// ---------------- build ------------------------------------------------------

__global__ void k_fill(const int* __restrict__ src, const int* __restrict__ dst) {
    int t = blockIdx.x * blockDim.x + threadIdx.x;
    int base = t * 8;
    if (base >= N_EDGES) return;
    int4 sa = *(const int4*)(src + base);
    int4 sb = *(const int4*)(src + base + 4);
    int4 da = *(const int4*)(dst + base);
    int4 db = *(const int4*)(dst + base + 4);
    atomicAdd(&g_degout[sa.x], 1); atomicAdd(&g_degout[sa.y], 1);
    atomicAdd(&g_degout[sa.z], 1); atomicAdd(&g_degout[sa.w], 1);
    atomicAdd(&g_degout[sb.x], 1); atomicAdd(&g_degout[sb.y], 1);
    atomicAdd(&g_degout[sb.z], 1); atomicAdd(&g_degout[sb.w], 1);
    int p0 = atomicAdd(&g_degin[da.x], 1);
    int p1 = atomicAdd(&g_degin[da.y], 1);
    int p2 = atomicAdd(&g_degin[da.z], 1);
    int p3 = atomicAdd(&g_degin[da.w], 1);
    int p4 = atomicAdd(&g_degin[db.x], 1);
    int p5 = atomicAdd(&g_degin[db.y], 1);
    int p6 = atomicAdd(&g_degin[db.z], 1);
    int p7 = atomicAdd(&g_degin[db.w], 1);
    g_ell[(size_t)da.x * ELL_W + p0] = sa.x;
    g_ell[(size_t)da.y * ELL_W + p1] = sa.y;
    g_ell[(size_t)da.z * ELL_W + p2] = sa.z;
    g_ell[(size_t)da.w * ELL_W + p3] = sa.w;
    g_ell[(size_t)db.x * ELL_W + p4] = sb.x;
    g_ell[(size_t)db.y * ELL_W + p5] = sb.y;
    g_ell[(size_t)db.z * ELL_W + p6] = sb.z;
    g_ell[(size_t)db.w * ELL_W + p7] = sb.w;
}

__global__ void k_prep(const float* __restrict__ n_feat) {
    int i = blockIdx.x * blockDim.x + threadIdx.x;
    if (i >= N_NODES) return;
    int deg = g_degin[i];
    float io = rsqrtf(fmaxf((float)g_degout[i], 1.f));
    float ii = rsqrtf(fmaxf((float)deg, 1.f));
    g_invin[i]  = ii;
    g_invout[i] = io;
    int deg4 = (deg + 3) & ~3;
    int* row = g_ell + (size_t)i * ELL_W;
    for (int e = deg; e < deg4; e++) row[e] = SENT;
    const float4* xr = (const float4*)(n_feat + (size_t)i * 8);
    float4 a = xr[0], b = xr[1];
    __half2 hv[4];
    hv[0] = __floats2half2_rn(a.x * io, a.y * io);
    hv[1] = __floats2half2_rn(a.z * io, a.w * io);
    hv[2] = __floats2half2_rn(b.x * io, b.y * io);
    hv[3] = __floats2half2_rn(b.z * io, b.w * io);
    *(uint4*)(g_x1h + (size_t)i * 4) = *(uint4*)hv;
}

// ---------------- layers: 2 lanes per node ------------------------------------

// Layer 1: lanes split EDGES (2 per 4-group each); merge a[8] via 8 shfl;
// each lane computes+writes 8 of 16 outputs.
__global__ void __launch_bounds__(256, 4) k_layer1(const float* __restrict__ W1,
                                                   const float* __restrict__ b1) {
    __shared__ float sW[8 * 16];
    __shared__ float sb[16];
    int t = threadIdx.x;
    if (t < 128) sW[t] = W1[t];
    if (t < 16)  sb[t] = b1[t];
    __syncthreads();
    int gt = blockIdx.x * blockDim.x + t;
    int i = gt >> 1;
    int half = gt & 1;
    bool valid = (i < N_NODES);
    int ic = valid ? i : 0;
    int deg4 = valid ? ((g_degin[ic] + 3) & ~3) : 0;
    const int* row = g_ell + (size_t)ic * ELL_W;
    float a[8];
    #pragma unroll
    for (int j = 0; j < 8; j++) a[j] = 0.f;
    for (int e = half * 2; e < deg4; e += 4) {
        int2 s = *(const int2*)(row + e);                 // 8B-aligned (e even)
        uint4 u0 = *(const uint4*)(g_x1h + (size_t)s.x * 4);
        uint4 u1 = *(const uint4*)(g_x1h + (size_t)s.y * 4);
        tree2(a[0], a[1], u0.x, u1.x);
        tree2(a[2], a[3], u0.y, u1.y);
        tree2(a[4], a[5], u0.z, u1.z);
        tree2(a[6], a[7], u0.w, u1.w);
    }
    #pragma unroll
    for (int j = 0; j < 8; j++)
        a[j] += __shfl_xor_sync(0xffffffffu, a[j], 1);
    float ii = valid ? g_invin[ic] : 0.f;
    float io = valid ? g_invout[ic] : 0.f;
    #pragma unroll
    for (int j = 0; j < 8; j++) a[j] *= ii;
    __half2 hv[4];
    #pragma unroll
    for (int v = 0; v < 4; v++) {
        int c0 = half * 8 + 2 * v;
        float s0 = sb[c0], s1 = sb[c0 + 1];
        #pragma unroll
        for (int k = 0; k < 8; k++) {
            s0 = fmaf(a[k], sW[k * 16 + c0],     s0);
            s1 = fmaf(a[k], sW[k * 16 + c0 + 1], s1);
        }
        hv[v] = __floats2half2_rn(fmaxf(s0, 0.f) * io, fmaxf(s1, 0.f) * io);
    }
    if (valid)
        *(uint4*)(g_h1s + (size_t)i * 8 + half * 4) = *(uint4*)hv;
}

// Layer 2+3a: lanes split FEATURES (16B half-row each; gathers coalesce into
// the same 32B row); 8-shfl exchange -> full a[16]; each lane does 16 of 32
// h2 columns; 10-shfl z merge; split store. Forced 3 blocks/SM.
__global__ void __launch_bounds__(256, 3) k_layer2(const float* __restrict__ W2,
                                                   const float* __restrict__ b2,
                                                   const float* __restrict__ W3) {
    __shared__ float sW2[16 * 32];
    __shared__ float sb2[32];
    __shared__ float sW3[32 * 10];
    int t = threadIdx.x;
    for (int j = t; j < 16 * 32; j += blockDim.x) sW2[j] = W2[j];
    for (int j = t; j < 32 * 10; j += blockDim.x) sW3[j] = W3[j];
    if (t < 32) sb2[t] = b2[t];
    __syncthreads();
    int gt = blockIdx.x * blockDim.x + t;
    int i = gt >> 1;
    int half = gt & 1;
    bool valid = (i < N_NODES);
    int ic = valid ? i : 0;
    int deg4 = valid ? ((g_degin[ic] + 3) & ~3) : 0;
    const int* row = g_ell + (size_t)ic * ELL_W;
    float a[8];
    #pragma unroll
    for (int j = 0; j < 8; j++) a[j] = 0.f;
    const __half2* basep = g_h1s + half * 4;   // lane's feature half
    for (int e = 0; e < deg4; e += 4) {
        int4 s = *(const int4*)(row + e);      // same addr both lanes -> broadcast
        uint4 u0 = *(const uint4*)(basep + (size_t)s.x * 8);
        uint4 u1 = *(const uint4*)(basep + (size_t)s.y * 8);
        uint4 u2 = *(const uint4*)(basep + (size_t)s.z * 8);
        uint4 u3 = *(const uint4*)(basep + (size_t)s.w * 8);
        tree4(a[0], a[1], u0.x, u1.x, u2.x, u3.x);
        tree4(a[2], a[3], u0.y, u1.y, u2.y, u3.y);
        tree4(a[4], a[5], u0.z, u1.z, u2.z, u3.z);
        tree4(a[6], a[7], u0.w, u1.w, u2.w, u3.w);
    }
    float ii = valid ? g_invin[ic] : 0.f;
    float io = valid ? g_invout[ic] : 0.f;
    #pragma unroll
    for (int j = 0; j < 8; j++) a[j] *= ii;
    float af[16];
    #pragma unroll
    for (int j = 0; j < 8; j++) {
        float mine = a[j];
        float theirs = __shfl_xor_sync(0xffffffffu, mine, 1);
        af[j]     = half ? theirs : mine;   // features 0..7
        af[j + 8] = half ? mine  : theirs;  // features 8..15
    }
    float z[10];
    #pragma unroll
    for (int j = 0; j < 10; j++) z[j] = 0.f;
    int kbase = half * 16;
    #pragma unroll
    for (int kk = 0; kk < 16; kk++) {
        int k = kbase + kk;
        float s = sb2[k];
        #pragma unroll
        for (int j = 0; j < 16; j++)
            s = fmaf(af[j], sW2[j * 32 + k], s);
        float h = fmaxf(s, 0.f) * io;
        #pragma unroll
        for (int j = 0; j < 10; j++)
            z[j] = fmaf(h, sW3[k * 10 + j], z[j]);
    }
    #pragma unroll
    for (int j = 0; j < 10; j++)
        z[j] += __shfl_xor_sync(0xffffffffu, z[j], 1);
    if (valid) {
        __half2 hv[5];
        #pragma unroll
        for (int v = 0; v < 5; v++)
            hv[v] = __floats2half2_rn(z[2*v], z[2*v+1]);
        __half2* o = g_z3h + (size_t)i * 8;
        if (half == 0) *(uint4*)(o) = *(uint4*)(hv);
        else           *(unsigned*)(o + 4) = *(unsigned*)(hv + 4);
    }
}

__device__ __forceinline__ int lowerb(const int* __restrict__ a, int n, int v) {
    int lo = 0, hi = n;
    while (lo < hi) {
        int m = (lo + hi) >> 1;
        if (a[m] < v) lo = m + 1; else hi = m;
    }
    return lo;
}

// Layer 3b + pool + fused finalizer. 2 lanes/node split EDGES; pool butterfly
// merges lanes for free. Forced 2 blocks/SM.
__global__ void __launch_bounds__(512, 2) k_layer3(const int* __restrict__ gids,
                                                   const float* __restrict__ b3,
                                                   float* __restrict__ out) {
    __shared__ float ssum[N_GRAPHS * 10];
    int t = threadIdx.x;
    for (int j = t; j < N_GRAPHS * 10; j += blockDim.x) ssum[j] = 0.f;
    __syncthreads();
    int gt = blockIdx.x * blockDim.x + t;
    int i = gt >> 1;
    int half = gt & 1;
    float v[10];
    #pragma unroll
    for (int j = 0; j < 10; j++) v[j] = 0.f;
    int g = -1;
    if (i < N_NODES) {
        int deg4 = (g_degin[i] + 3) & ~3;
        const int* row = g_ell + (size_t)i * ELL_W;
        for (int e = half * 2; e < deg4; e += 4) {
            int2 s = *(const int2*)(row + e);
            const __half2* r0 = g_z3h + (size_t)s.x * 8;
            const __half2* r1 = g_z3h + (size_t)s.y * 8;
            uint4 u0 = *(const uint4*)r0;  unsigned w0 = *(const unsigned*)(r0 + 4);
            uint4 u1 = *(const uint4*)r1;  unsigned w1 = *(const unsigned*)(r1 + 4);
            tree2(v[0], v[1], u0.x, u1.x);
            tree2(v[2], v[3], u0.y, u1.y);
            tree2(v[4], v[5], u0.z, u1.z);
            tree2(v[6], v[7], u0.w, u1.w);
            tree2(v[8], v[9], w0, w1);
        }
        float ii = g_invin[i];
        #pragma unroll
        for (int j = 0; j < 10; j++) v[j] *= ii;
        g = gids[i];
        g_degin[i]  = 0;
        g_degout[i] = 0;
    }
    int leader = __shfl_sync(0xffffffffu, g, 0);
    bool uni = __all_sync(0xffffffffu, g == leader);
    if (uni && leader >= 0) {
        #pragma unroll
        for (int j = 0; j < 10; j++) {
            float s = v[j];
            #pragma unroll
            for (int off = 16; off > 0; off >>= 1)
                s += __shfl_xor_sync(0xffffffffu, s, off);
            if ((t & 31) == 0) atomicAdd(&ssum[leader * 10 + j], s);
        }
    } else if (g >= 0) {
        #pragma unroll
        for (int j = 0; j < 10; j++)
            atomicAdd(&ssum[g * 10 + j], v[j]);
    }
    __syncthreads();
    for (int j = t; j < N_GRAPHS * 10; j += blockDim.x) {
        float s = ssum[j];
        if (s != 0.f) atomicAdd(&g_gsum[j], s);
    }
    __threadfence();
    __shared__ int s_last;
    __syncthreads();
    if (t == 0) {
        int d = atomicAdd(&g_done, 1);
        s_last = (d == (int)gridDim.x - 1);
    }
    __syncthreads();
    if (s_last) {
        for (int o = t; o < N_GRAPHS * 10; o += blockDim.x) {
            int gg = o / 10, j = o % 10;
            int lo = lowerb(gids, N_NODES, gg);
            int hi = lowerb(gids, N_NODES, gg + 1);
            float cnt = (float)(hi - lo);
            out[o] = g_gsum[o] / fmaxf(cnt, 1.f) + b3[j];
            g_gsum[o] = 0.f;
        }
        if (t == 0) g_done = 0;
    }
}

// ---------------- launch ------------------------------------------------------
extern "C" void kernel_launch(void* const* d_in, const int* in_sizes, int n_in,
                              void* d_out, int out_size) {
    const float* n_feat = (const float*)d_in[0];
    const int*   src    = (const int*)  d_in[1];
    const int*   dst    = (const int*)  d_in[2];
    const int*   gids   = (const int*)  d_in[3];
    const float* W1     = (const float*)d_in[4];
    const float* b1     = (const float*)d_in[5];
    const float* W2     = (const float*)d_in[6];
    const float* b2     = (const float*)d_in[7];
    const float* W3     = (const float*)d_in[8];
    const float* b3     = (const float*)d_in[9];
    float* out = (float*)d_out;

    const int nb256 = (N_NODES + 255) / 256;            // 391
    const int eb8   = (N_EDGES / 8 + 255) / 256;
    const int lb2   = (2 * N_NODES + 255) / 256;        // 782 (2 lanes/node)
    const int lb512 = (2 * N_NODES + 511) / 512;        // 391

    k_fill   <<<eb8, 256>>>(src, dst);
    k_prep   <<<nb256, 256>>>(n_feat);
    k_layer1 <<<lb2, 256>>>(W1, b1);
    k_layer2 <<<lb2, 256>>>(W2, b2, W3);
    k_layer3 <<<lb512, 512>>>(gids, b3, out);
}

// round 16
// speedup vs baseline: 1.0413x; 1.0413x over previous
#include <cuda_runtime.h>
#include <cuda_fp16.h>

#define N_NODES  100000
#define N_EDGES  1600000
#define N_GRAPHS 64
#define ELL_W    64          // max in-degree pad (P(deg>64) ~ 1e-20)
#define SENT     N_NODES     // sentinel node id -> zero row

// ---------------- scratch (device globals; zero-init at load) ----------------
// INVARIANT: g_degout, g_degin, g_gsum, g_done are zero on entry to every
// kernel_launch call and are restored to zero by the end of it.
// Row SENT (=N_NODES) of g_x1h/g_h1s/g_z3h is NEVER written -> stays zero.
__device__ __align__(256) __half2  g_x1h  [(N_NODES + 1) * 4];
__device__ __align__(256) __half2  g_h1s  [(N_NODES + 1) * 8];
__device__ __align__(256) __half2  g_z3h  [(N_NODES + 1) * 8];
__device__ __align__(256) float    g_invin [N_NODES];
__device__ __align__(256) float    g_invout[N_NODES];
__device__ __align__(256) int      g_degout[N_NODES];
__device__ __align__(256) int      g_degin [N_NODES];
__device__ __align__(256) int      g_ell   [(size_t)N_NODES * ELL_W + 8];  // +8: prefetch pad
__device__ __align__(256) float    g_gsum [N_GRAPHS * 10];
__device__                int      g_done;

__device__ __forceinline__ __half2 h2(unsigned b) {
    return *reinterpret_cast<__half2*>(&b);
}
__device__ __forceinline__ void acc_f(float& a0, float& a1, __half2 h) {
    float2 f = __half22float2(h);
    a0 += f.x; a1 += f.y;
}
__device__ __forceinline__ void tree4(float& a0, float& a1,
                                      unsigned b0, unsigned b1,
                                      unsigned b2, unsigned b3) {
    __half2 t0 = __hadd2(h2(b0), h2(b1));
    __half2 t1 = __hadd2(h2(b2), h2(b3));
    acc_f(a0, a1, __hadd2(t0, t1));
}
__device__ __forceinline__ void tree2(float& a0, float& a1,
                                      unsigned b0, unsigned b1) {
    acc_f(a0, a1, __hadd2(h2(b0), h2(b1)));
}

// ---------------- build ------------------------------------------------------

__global__ void k_fill(const int* __restrict__ src, const int* __restrict__ dst) {
    int t = blockIdx.x * blockDim.x + threadIdx.x;
    int base = t * 8;
    if (base >= N_EDGES) return;
    int4 sa = *(const int4*)(src + base);
    int4 sb = *(const int4*)(src + base + 4);
    int4 da = *(const int4*)(dst + base);
    int4 db = *(const int4*)(dst + base + 4);
    atomicAdd(&g_degout[sa.x], 1); atomicAdd(&g_degout[sa.y], 1);
    atomicAdd(&g_degout[sa.z], 1); atomicAdd(&g_degout[sa.w], 1);
    atomicAdd(&g_degout[sb.x], 1); atomicAdd(&g_degout[sb.y], 1);
    atomicAdd(&g_degout[sb.z], 1); atomicAdd(&g_degout[sb.w], 1);
    int p0 = atomicAdd(&g_degin[da.x], 1);
    int p1 = atomicAdd(&g_degin[da.y], 1);
    int p2 = atomicAdd(&g_degin[da.z], 1);
    int p3 = atomicAdd(&g_degin[da.w], 1);
    int p4 = atomicAdd(&g_degin[db.x], 1);
    int p5 = atomicAdd(&g_degin[db.y], 1);
    int p6 = atomicAdd(&g_degin[db.z], 1);
    int p7 = atomicAdd(&g_degin[db.w], 1);
    g_ell[(size_t)da.x * ELL_W + p0] = sa.x;
    g_ell[(size_t)da.y * ELL_W + p1] = sa.y;
    g_ell[(size_t)da.z * ELL_W + p2] = sa.z;
    g_ell[(size_t)da.w * ELL_W + p3] = sa.w;
    g_ell[(size_t)db.x * ELL_W + p4] = sb.x;
    g_ell[(size_t)db.y * ELL_W + p5] = sb.y;
    g_ell[(size_t)db.z * ELL_W + p6] = sb.z;
    g_ell[(size_t)db.w * ELL_W + p7] = sb.w;
}

__global__ void k_prep(const float* __restrict__ n_feat) {
    int i = blockIdx.x * blockDim.x + threadIdx.x;
    if (i >= N_NODES) return;
    int deg = g_degin[i];
    float io = rsqrtf(fmaxf((float)g_degout[i], 1.f));
    float ii = rsqrtf(fmaxf((float)deg, 1.f));
    g_invin[i]  = ii;
    g_invout[i] = io;
    int deg4 = (deg + 3) & ~3;
    int* row = g_ell + (size_t)i * ELL_W;
    for (int e = deg; e < deg4; e++) row[e] = SENT;
    const float4* xr = (const float4*)(n_feat + (size_t)i * 8);
    float4 a = xr[0], b = xr[1];
    __half2 hv[4];
    hv[0] = __floats2half2_rn(a.x * io, a.y * io);
    hv[1] = __floats2half2_rn(a.z * io, a.w * io);
    hv[2] = __floats2half2_rn(b.x * io, b.y * io);
    hv[3] = __floats2half2_rn(b.z * io, b.w * io);
    *(uint4*)(g_x1h + (size_t)i * 4) = *(uint4*)hv;
}

// ---------------- layers: 2 lanes per node, pipelined index prefetch ----------

// Layer 1: lanes split EDGES (2 per 4-group each); merge a[8] via 8 shfl;
// each lane computes+writes 8 of 16 outputs.
__global__ void __launch_bounds__(256) k_layer1(const float* __restrict__ W1,
                                                const float* __restrict__ b1) {
    __shared__ float sW[8 * 16];
    __shared__ float sb[16];
    int t = threadIdx.x;
    if (t < 128) sW[t] = W1[t];
    if (t < 16)  sb[t] = b1[t];
    __syncthreads();
    int gt = blockIdx.x * blockDim.x + t;
    int i = gt >> 1;
    int half = gt & 1;
    bool valid = (i < N_NODES);
    int ic = valid ? i : 0;
    int deg4 = valid ? ((g_degin[ic] + 3) & ~3) : 0;
    const int* row = g_ell + (size_t)ic * ELL_W;
    float a[8];
    #pragma unroll
    for (int j = 0; j < 8; j++) a[j] = 0.f;
    int2 s = *(const int2*)(row + half * 2);          // prime the pipeline
    for (int e = half * 2; e < deg4; e += 4) {
        int2 sn = *(const int2*)(row + e + 4);        // prefetch next (pad-safe)
        uint4 u0 = *(const uint4*)(g_x1h + (size_t)s.x * 4);
        uint4 u1 = *(const uint4*)(g_x1h + (size_t)s.y * 4);
        tree2(a[0], a[1], u0.x, u1.x);
        tree2(a[2], a[3], u0.y, u1.y);
        tree2(a[4], a[5], u0.z, u1.z);
        tree2(a[6], a[7], u0.w, u1.w);
        s = sn;
    }
    #pragma unroll
    for (int j = 0; j < 8; j++)
        a[j] += __shfl_xor_sync(0xffffffffu, a[j], 1);
    float ii = valid ? g_invin[ic] : 0.f;
    float io = valid ? g_invout[ic] : 0.f;
    #pragma unroll
    for (int j = 0; j < 8; j++) a[j] *= ii;
    __half2 hv[4];
    #pragma unroll
    for (int v = 0; v < 4; v++) {
        int c0 = half * 8 + 2 * v;
        float s0 = sb[c0], s1 = sb[c0 + 1];
        #pragma unroll
        for (int k = 0; k < 8; k++) {
            s0 = fmaf(a[k], sW[k * 16 + c0],     s0);
            s1 = fmaf(a[k], sW[k * 16 + c0 + 1], s1);
        }
        hv[v] = __floats2half2_rn(fmaxf(s0, 0.f) * io, fmaxf(s1, 0.f) * io);
    }
    if (valid)
        *(uint4*)(g_h1s + (size_t)i * 8 + half * 4) = *(uint4*)hv;
}

// Layer 2+3a: lanes split FEATURES (16B half-row each); pipelined index
// prefetch; 8-shfl exchange -> full a[16]; each lane does 16 of 32 h2 cols;
// 10-shfl z merge; split store.
__global__ void __launch_bounds__(256, 3) k_layer2(const float* __restrict__ W2,
                                                   const float* __restrict__ b2,
                                                   const float* __restrict__ W3) {
    __shared__ float sW2[16 * 32];
    __shared__ float sb2[32];
    __shared__ float sW3[32 * 10];
    int t = threadIdx.x;
    for (int j = t; j < 16 * 32; j += blockDim.x) sW2[j] = W2[j];
    for (int j = t; j < 32 * 10; j += blockDim.x) sW3[j] = W3[j];
    if (t < 32) sb2[t] = b2[t];
    __syncthreads();
    int gt = blockIdx.x * blockDim.x + t;
    int i = gt >> 1;
    int half = gt & 1;
    bool valid = (i < N_NODES);
    int ic = valid ? i : 0;
    int deg4 = valid ? ((g_degin[ic] + 3) & ~3) : 0;
    const int* row = g_ell + (size_t)ic * ELL_W;
    float a[8];
    #pragma unroll
    for (int j = 0; j < 8; j++) a[j] = 0.f;
    const __half2* basep = g_h1s + half * 4;   // lane's feature half
    int4 s = *(const int4*)(row);              // prime the pipeline
    for (int e = 0; e < deg4; e += 4) {
        int4 sn = *(const int4*)(row + e + 4); // prefetch next (pad-safe)
        uint4 u0 = *(const uint4*)(basep + (size_t)s.x * 8);
        uint4 u1 = *(const uint4*)(basep + (size_t)s.y * 8);
        uint4 u2 = *(const uint4*)(basep + (size_t)s.z * 8);
        uint4 u3 = *(const uint4*)(basep + (size_t)s.w * 8);
        tree4(a[0], a[1], u0.x, u1.x, u2.x, u3.x);
        tree4(a[2], a[3], u0.y, u1.y, u2.y, u3.y);
        tree4(a[4], a[5], u0.z, u1.z, u2.z, u3.z);
        tree4(a[6], a[7], u0.w, u1.w, u2.w, u3.w);
        s = sn;
    }
    float ii = valid ? g_invin[ic] : 0.f;
    float io = valid ? g_invout[ic] : 0.f;
    #pragma unroll
    for (int j = 0; j < 8; j++) a[j] *= ii;
    float af[16];
    #pragma unroll
    for (int j = 0; j < 8; j++) {
        float mine = a[j];
        float theirs = __shfl_xor_sync(0xffffffffu, mine, 1);
        af[j]     = half ? theirs : mine;   // features 0..7
        af[j + 8] = half ? mine  : theirs;  // features 8..15
    }
    float z[10];
    #pragma unroll
    for (int j = 0; j < 10; j++) z[j] = 0.f;
    int kbase = half * 16;
    #pragma unroll
    for (int kk = 0; kk < 16; kk++) {
        int k = kbase + kk;
        float sacc = sb2[k];
        #pragma unroll
        for (int j = 0; j < 16; j++)
            sacc = fmaf(af[j], sW2[j * 32 + k], sacc);
        float h = fmaxf(sacc, 0.f) * io;
        #pragma unroll
        for (int j = 0; j < 10; j++)
            z[j] = fmaf(h, sW3[k * 10 + j], z[j]);
    }
    #pragma unroll
    for (int j = 0; j < 10; j++)
        z[j] += __shfl_xor_sync(0xffffffffu, z[j], 1);
    if (valid) {
        __half2 hv[5];
        #pragma unroll
        for (int v = 0; v < 5; v++)
            hv[v] = __floats2half2_rn(z[2*v], z[2*v+1]);
        __half2* o = g_z3h + (size_t)i * 8;
        if (half == 0) *(uint4*)(o) = *(uint4*)(hv);
        else           *(unsigned*)(o + 4) = *(unsigned*)(hv + 4);
    }
}

__device__ __forceinline__ int lowerb(const int* __restrict__ a, int n, int v) {
    int lo = 0, hi = n;
    while (lo < hi) {
        int m = (lo + hi) >> 1;
        if (a[m] < v) lo = m + 1; else hi = m;
    }
    return lo;
}

// Layer 3b + pool + fused finalizer. 2 lanes/node split EDGES; pipelined
// index prefetch; pool butterfly merges lanes for free.
__global__ void __launch_bounds__(512) k_layer3(const int* __restrict__ gids,
                                                const float* __restrict__ b3,
                                                float* __restrict__ out) {
    __shared__ float ssum[N_GRAPHS * 10];
    int t = threadIdx.x;
    for (int j = t; j < N_GRAPHS * 10; j += blockDim.x) ssum[j] = 0.f;
    __syncthreads();
    int gt = blockIdx.x * blockDim.x + t;
    int i = gt >> 1;
    int half = gt & 1;
    float v[10];
    #pragma unroll
    for (int j = 0; j < 10; j++) v[j] = 0.f;
    int g = -1;
    if (i < N_NODES) {
        int deg4 = (g_degin[i] + 3) & ~3;
        const int* row = g_ell + (size_t)i * ELL_W;
        int2 s = *(const int2*)(row + half * 2);
        for (int e = half * 2; e < deg4; e += 4) {
            int2 sn = *(const int2*)(row + e + 4);
            const __half2* r0 = g_z3h + (size_t)s.x * 8;
            const __half2* r1 = g_z3h + (size_t)s.y * 8;
            uint4 u0 = *(const uint4*)r0;  unsigned w0 = *(const unsigned*)(r0 + 4);
            uint4 u1 = *(const uint4*)r1;  unsigned w1 = *(const unsigned*)(r1 + 4);
            tree2(v[0], v[1], u0.x, u1.x);
            tree2(v[2], v[3], u0.y, u1.y);
            tree2(v[4], v[5], u0.z, u1.z);
            tree2(v[6], v[7], u0.w, u1.w);
            tree2(v[8], v[9], w0, w1);
            s = sn;
        }
        float ii = g_invin[i];
        #pragma unroll
        for (int j = 0; j < 10; j++) v[j] *= ii;
        g = gids[i];
        g_degin[i]  = 0;
        g_degout[i] = 0;
    }
    int leader = __shfl_sync(0xffffffffu, g, 0);
    bool uni = __all_sync(0xffffffffu, g == leader);
    if (uni && leader >= 0) {
        #pragma unroll
        for (int j = 0; j < 10; j++) {
            float s = v[j];
            #pragma unroll
            for (int off = 16; off > 0; off >>= 1)
                s += __shfl_xor_sync(0xffffffffu, s, off);
            if ((t & 31) == 0) atomicAdd(&ssum[leader * 10 + j], s);
        }
    } else if (g >= 0) {
        #pragma unroll
        for (int j = 0; j < 10; j++)
            atomicAdd(&ssum[g * 10 + j], v[j]);
    }
    __syncthreads();
    for (int j = t; j < N_GRAPHS * 10; j += blockDim.x) {
        float s = ssum[j];
        if (s != 0.f) atomicAdd(&g_gsum[j], s);
    }
    __threadfence();
    __shared__ int s_last;
    __syncthreads();
    if (t == 0) {
        int d = atomicAdd(&g_done, 1);
        s_last = (d == (int)gridDim.x - 1);
    }
    __syncthreads();
    if (s_last) {
        for (int o = t; o < N_GRAPHS * 10; o += blockDim.x) {
            int gg = o / 10, j = o % 10;
            int lo = lowerb(gids, N_NODES, gg);
            int hi = lowerb(gids, N_NODES, gg + 1);
            float cnt = (float)(hi - lo);
            out[o] = g_gsum[o] / fmaxf(cnt, 1.f) + b3[j];
            g_gsum[o] = 0.f;
        }
        if (t == 0) g_done = 0;
    }
}

// ---------------- launch ------------------------------------------------------
extern "C" void kernel_launch(void* const* d_in, const int* in_sizes, int n_in,
                              void* d_out, int out_size) {
    const float* n_feat = (const float*)d_in[0];
    const int*   src    = (const int*)  d_in[1];
    const int*   dst    = (const int*)  d_in[2];
    const int*   gids   = (const int*)  d_in[3];
    const float* W1     = (const float*)d_in[4];
    const float* b1     = (const float*)d_in[5];
    const float* W2     = (const float*)d_in[6];
    const float* b2     = (const float*)d_in[7];
    const float* W3     = (const float*)d_in[8];
    const float* b3     = (const float*)d_in[9];
    float* out = (float*)d_out;

    const int nb256 = (N_NODES + 255) / 256;            // 391
    const int eb8   = (N_EDGES / 8 + 255) / 256;
    const int lb2   = (2 * N_NODES + 255) / 256;        // 782 (2 lanes/node)
    const int lb512 = (2 * N_NODES + 511) / 512;        // 391

    k_fill   <<<eb8, 256>>>(src, dst);
    k_prep   <<<nb256, 256>>>(n_feat);
    k_layer1 <<<lb2, 256>>>(W1, b1);
    k_layer2 <<<lb2, 256>>>(W2, b2, W3);
    k_layer3 <<<lb512, 512>>>(gids, b3, out);
}